// round 2
// baseline (speedup 1.0000x reference)
#include <cuda_runtime.h>
#include <cstdint>

// EdgewiseReduce: out[dst[e], :] += 0.5 * edge_data[e, :], D=32, E=1.6M, N=100K.
// edge_dst is int32 on device (JAX x64-disabled downcasts the requested int64).
// Strategy: zero output, then warp-coalesced scatter with red.global.add.v4.f32
// (no-return vector atomic; 8 REDs per edge instead of 32 scalar atomics).

#define FACTOR 0.5f
#define D 32
#define D4 8  // float4 chunks per edge

__global__ void zero_out_kernel(float4* __restrict__ out, int n4) {
    int i = blockIdx.x * blockDim.x + threadIdx.x;
    if (i < n4) out[i] = make_float4(0.f, 0.f, 0.f, 0.f);
}

__global__ void scatter_add_kernel(const float4* __restrict__ edge_data,
                                   const int* __restrict__ edge_dst,
                                   float* __restrict__ out,
                                   int num_edges) {
    int tid = blockIdx.x * blockDim.x + threadIdx.x;
    int e = tid >> 3;        // edge index
    int c = tid & 7;         // float4 chunk within the edge (0..7)
    if (e >= num_edges) return;

    // 8 consecutive threads share one edge: edge_dst load broadcasts in-warp,
    // edge_data float4 loads are fully coalesced.
    int dst = edge_dst[e];
    float4 v = edge_data[(size_t)e * D4 + c];

    float x = v.x * FACTOR;
    float y = v.y * FACTOR;
    float z = v.z * FACTOR;
    float w = v.w * FACTOR;

    float* p = out + (size_t)dst * D + c * 4;
    asm volatile("red.global.add.v4.f32 [%0], {%1, %2, %3, %4};"
                 :: "l"(p), "f"(x), "f"(y), "f"(z), "f"(w)
                 : "memory");
}

extern "C" void kernel_launch(void* const* d_in, const int* in_sizes, int n_in,
                              void* d_out, int out_size) {
    const float4* edge_data = (const float4*)d_in[0];
    const int*    edge_dst  = (const int*)d_in[1];
    float* out = (float*)d_out;

    int num_edges = in_sizes[1];       // E (element count of edge_dst)

    // 1) Zero the output (harness poisons it with 0xAA).
    int n4 = out_size / 4;
    int zb = (n4 + 255) / 256;
    zero_out_kernel<<<zb, 256>>>((float4*)out, n4);

    // 2) Scatter-add: 8 threads per edge.
    long long total = (long long)num_edges * D4;
    int sb = (int)((total + 255) / 256);
    scatter_add_kernel<<<sb, 256>>>(edge_data, edge_dst, out, num_edges);
}

// round 3
// speedup vs baseline: 1.0869x; 1.0869x over previous
#include <cuda_runtime.h>
#include <cstdint>

// EdgewiseReduce: out[dst[e], :] += 0.5 * edge_data[e, :], D=32, E=1.6M, N=100K.
// edge_dst is int32 on device. Strategy: memset output, then grid-stride scatter
// with 4-way unrolled red.global.add.v4.f32 for MLP (latency hiding).

#define FACTOR 0.5f
#define D 32
#define D4 8         // float4 chunks per edge
#define UNROLL 4

__global__ void scatter_add_kernel(const float4* __restrict__ edge_data,
                                   const int* __restrict__ edge_dst,
                                   float* __restrict__ out,
                                   long long total_chunks) {
    const long long stride = (long long)blockDim.x * gridDim.x;
    long long i = (long long)blockIdx.x * blockDim.x + threadIdx.x;

    // Main unrolled loop: 4 independent chunk-transactions in flight per thread.
    for (; i + 3 * stride < total_chunks; i += UNROLL * stride) {
        long long i0 = i, i1 = i + stride, i2 = i + 2 * stride, i3 = i + 3 * stride;

        // Front-batch all loads (ptxas will keep these outstanding together).
        int d0 = edge_dst[i0 >> 3];
        int d1 = edge_dst[i1 >> 3];
        int d2 = edge_dst[i2 >> 3];
        int d3 = edge_dst[i3 >> 3];
        float4 v0 = edge_data[i0];
        float4 v1 = edge_data[i1];
        float4 v2 = edge_data[i2];
        float4 v3 = edge_data[i3];

        float* p0 = out + (size_t)d0 * D + (i0 & 7) * 4;
        float* p1 = out + (size_t)d1 * D + (i1 & 7) * 4;
        float* p2 = out + (size_t)d2 * D + (i2 & 7) * 4;
        float* p3 = out + (size_t)d3 * D + (i3 & 7) * 4;

        asm volatile("red.global.add.v4.f32 [%0], {%1, %2, %3, %4};"
                     :: "l"(p0), "f"(v0.x * FACTOR), "f"(v0.y * FACTOR),
                        "f"(v0.z * FACTOR), "f"(v0.w * FACTOR) : "memory");
        asm volatile("red.global.add.v4.f32 [%0], {%1, %2, %3, %4};"
                     :: "l"(p1), "f"(v1.x * FACTOR), "f"(v1.y * FACTOR),
                        "f"(v1.z * FACTOR), "f"(v1.w * FACTOR) : "memory");
        asm volatile("red.global.add.v4.f32 [%0], {%1, %2, %3, %4};"
                     :: "l"(p2), "f"(v2.x * FACTOR), "f"(v2.y * FACTOR),
                        "f"(v2.z * FACTOR), "f"(v2.w * FACTOR) : "memory");
        asm volatile("red.global.add.v4.f32 [%0], {%1, %2, %3, %4};"
                     :: "l"(p3), "f"(v3.x * FACTOR), "f"(v3.y * FACTOR),
                        "f"(v3.z * FACTOR), "f"(v3.w * FACTOR) : "memory");
    }

    // Tail.
    for (; i < total_chunks; i += stride) {
        int d = edge_dst[i >> 3];
        float4 v = edge_data[i];
        float* p = out + (size_t)d * D + (i & 7) * 4;
        asm volatile("red.global.add.v4.f32 [%0], {%1, %2, %3, %4};"
                     :: "l"(p), "f"(v.x * FACTOR), "f"(v.y * FACTOR),
                        "f"(v.z * FACTOR), "f"(v.w * FACTOR) : "memory");
    }
}

extern "C" void kernel_launch(void* const* d_in, const int* in_sizes, int n_in,
                              void* d_out, int out_size) {
    const float4* edge_data = (const float4*)d_in[0];
    const int*    edge_dst  = (const int*)d_in[1];
    float* out = (float*)d_out;

    int num_edges = in_sizes[1];                       // E
    long long total_chunks = (long long)num_edges * D4; // E*8 float4 chunks

    // 1) Zero output via graph-capturable memset node (harness poisons with 0xAA).
    cudaMemsetAsync(d_out, 0, (size_t)out_size * sizeof(float), 0);

    // 2) Scatter-add, 4 chunks per thread.
    const int threads = 256;
    long long want = (total_chunks + (long long)threads * UNROLL - 1) /
                     ((long long)threads * UNROLL);
    int blocks = (int)(want > 1000000 ? 1000000 : want);
    if (blocks < 1) blocks = 1;
    scatter_add_kernel<<<blocks, threads>>>(edge_data, edge_dst, out, total_chunks);
}